// round 15
// baseline (speedup 1.0000x reference)
#include <cuda_runtime.h>
#include <math.h>

#define BB 8
#define NN 10000
#define EE 320000
#define IND 16
#define EH 32
#define EO 22
#define NOUT 16

typedef unsigned long long u64;

#define NLOG2E (-1.4426950408889634f)

// ---------------- scratch (device globals; no allocations) ----------------
__device__ float2 g_u[NN * (EH / 2) * BB];   // [node][p][b], pre-scaled by -log2e
__device__ float2 g_v[NN * (EH / 2) * BB];
__device__ float2 g_sw[NN * BB];             // (speed*cos, speed*sin)
__device__ float4 g_agg2[NN * BB * (NOUT / 4)];  // accumulator [n][b][16] (scaled)
__device__ float4 g_erec[EE];                // {cosc/dist, sinc/dist, n0, n1}
__device__ int2   g_eidx[EE];
__device__ float4 g_serec[EE];               // sorted-by-src
__device__ int2   g_seidx[EE];
__device__ int    g_minmax[4];
__device__ int    g_is_i32;
__device__ int    g_cnt[NN];
__device__ int    g_off[NN];

// ---------------- f32x2 helpers ----------------
__device__ __forceinline__ u64 pack2(float lo, float hi) {
    u64 r; asm("mov.b64 %0, {%1, %2};" : "=l"(r) : "f"(lo), "f"(hi)); return r;
}
__device__ __forceinline__ u64 bcast2(float v) { return pack2(v, v); }
__device__ __forceinline__ void unpack2(u64 v, float& lo, float& hi) {
    asm("mov.b64 {%0, %1}, %2;" : "=f"(lo), "=f"(hi) : "l"(v));
}
__device__ __forceinline__ u64 fma2(u64 a, u64 b, u64 c) {
    u64 d; asm("fma.rn.f32x2 %0, %1, %2, %3;" : "=l"(d) : "l"(a), "l"(b), "l"(c)); return d;
}
__device__ __forceinline__ u64 add2(u64 a, u64 b) {
    u64 d; asm("add.rn.f32x2 %0, %1, %2;" : "=l"(d) : "l"(a), "l"(b)); return d;
}
__device__ __forceinline__ u64 ld2(const float2* p) {
    float2 t = *p; return pack2(t.x, t.y);
}
__device__ __forceinline__ void red4(float* p, float a, float b, float c, float d) {
    asm volatile("red.global.add.v4.f32 [%0], {%1, %2, %3, %4};"
                 :: "l"(p), "f"(a), "f"(b), "f"(c), "f"(d) : "memory");
}

// sigmoid with -log2e pre-folded into the argument: sig = rcp(1 + 2^x)
__device__ __forceinline__ float sigp(float x) {
    float e, r;
    asm("ex2.approx.f32 %0, %1;" : "=f"(e) : "f"(x));
    asm("rcp.approx.f32 %0, %1;" : "=f"(r) : "f"(1.0f + e));
    return r;
}

// ---------------- kernels ----------------
// tiny init: scalars + cnt only (agg zero folded into k_node)
__global__ void k_init() {
    int i = blockIdx.x * blockDim.x + threadIdx.x;
    int stride = gridDim.x * blockDim.x;
    for (int j = i; j < NN; j += stride) g_cnt[j] = 0;
    if (blockIdx.x == 0 && threadIdx.x == 0) {
        g_minmax[0] = 0x7F800000; g_minmax[1] = 0x7F800000;
        g_minmax[2] = 0;          g_minmax[3] = 0;
        g_is_i32 = 0;
    }
}

// fused: int32/int64 sniff + edge_attr min/max in one pass kernel
__global__ void k_minmax(const int* __restrict__ w32, const float* __restrict__ ea) {
    int i0 = blockIdx.x * blockDim.x + threadIdx.x;
    int stride = gridDim.x * blockDim.x;
    int hit = 0;
    for (int i = i0; i < EE; i += stride) hit |= (w32[2 * i + 1] != 0);
    float mn0 = 1e30f, mn1 = 1e30f, mx0 = -1e30f, mx1 = -1e30f;
    for (int i = i0; i < EE; i += stride) {
        float a = ea[2 * i], b = ea[2 * i + 1];
        mn0 = fminf(mn0, a); mx0 = fmaxf(mx0, a);
        mn1 = fminf(mn1, b); mx1 = fmaxf(mx1, b);
    }
    #pragma unroll
    for (int o = 16; o; o >>= 1) {
        mn0 = fminf(mn0, __shfl_xor_sync(0xFFFFFFFFu, mn0, o));
        mn1 = fminf(mn1, __shfl_xor_sync(0xFFFFFFFFu, mn1, o));
        mx0 = fmaxf(mx0, __shfl_xor_sync(0xFFFFFFFFu, mx0, o));
        mx1 = fmaxf(mx1, __shfl_xor_sync(0xFFFFFFFFu, mx1, o));
    }
    if ((threadIdx.x & 31) == 0) {
        atomicMin(&g_minmax[0], __float_as_int(mn0));
        atomicMin(&g_minmax[1], __float_as_int(mn1));
        atomicMax(&g_minmax[2], __float_as_int(mx0));
        atomicMax(&g_minmax[3], __float_as_int(mx1));
    }
    hit = __syncthreads_or(hit);
    if (threadIdx.x == 0 && hit) g_is_i32 = 1;
}

__global__ void k_erec(const int* __restrict__ ew32, const float* __restrict__ ea) {
    int e = blockIdx.x * blockDim.x + threadIdx.x;
    if (e >= EE) return;
    float d = ea[2 * e], dir = ea[2 * e + 1];
    float mn0 = __int_as_float(g_minmax[0]), mn1 = __int_as_float(g_minmax[1]);
    float mx0 = __int_as_float(g_minmax[2]), mx1 = __int_as_float(g_minmax[3]);
    float n0 = (d - mn0) / (mx0 - mn0);
    float n1 = (dir - mn1) / (mx1 - mn1);
    float sd, cd;
    sincosf(dir, &sd, &cd);
    float inv = 1.0f / d;
    g_erec[e] = make_float4(cd * inv, sd * inv, n0, n1);
    int s, t;
    if (g_is_i32) { s = ew32[e];     t = ew32[EE + e]; }
    else          { s = ew32[2 * e]; t = ew32[2 * (EE + e)]; }
    s = min(max(s, 0), NN - 1);
    t = min(max(t, 0), NN - 1);
    g_eidx[e] = make_int2(s, t);
    atomicAdd(&g_cnt[s], 1);
}

__global__ void k_scan() {
    __shared__ int ps[1024];
    int tid = threadIdx.x;
    int base = tid * 10;
    int loc[10]; int s = 0;
    #pragma unroll
    for (int i = 0; i < 10; i++) {
        int idx = base + i;
        int c = (idx < NN) ? g_cnt[idx] : 0;
        loc[i] = s; s += c;
    }
    ps[tid] = s;
    int total = s;
    __syncthreads();
    for (int off = 1; off < 1024; off <<= 1) {
        int t = (tid >= off) ? ps[tid - off] : 0;
        __syncthreads();
        ps[tid] += t;
        __syncthreads();
    }
    int excl = ps[tid] - total;
    #pragma unroll
    for (int i = 0; i < 10; i++) {
        int idx = base + i;
        if (idx < NN) g_off[idx] = excl + loc[i];
    }
}

__global__ void k_place() {
    int e = blockIdx.x * blockDim.x + threadIdx.x;
    if (e >= EE) return;
    int2 st = g_eidx[e];
    int pos = atomicAdd(&g_off[st.x], 1);
    g_seidx[pos] = st;
    g_serec[pos] = g_erec[e];
}

__global__ void k_node(const float* __restrict__ x, const float* __restrict__ W1,
                       const float* __restrict__ wmin, const float* __restrict__ wmax) {
    __shared__ float w1s[2 * IND][EH];
    for (int i = threadIdx.x; i < 2 * IND * EH; i += blockDim.x)
        w1s[i / EH][i % EH] = W1[i];
    __syncthreads();
    int idx = blockIdx.x * blockDim.x + threadIdx.x;
    if (idx >= BB * NN) return;
    int b = idx / NN, node = idx - b * NN;
    // zero this thread's agg row [node][b][16] (runs before k_edge)
    {
        float4 z = make_float4(0.f, 0.f, 0.f, 0.f);
        float4* row = g_agg2 + ((size_t)node * BB + b) * (NOUT / 4);
        row[0] = z; row[1] = z; row[2] = z; row[3] = z;
    }
    float xv[IND];
    const float4* xp = (const float4*)(x + (size_t)idx * IND);
    #pragma unroll
    for (int q = 0; q < 4; q++) {
        float4 t = xp[q];
        xv[4*q] = t.x; xv[4*q+1] = t.y; xv[4*q+2] = t.z; xv[4*q+3] = t.w;
    }
    float u[EH], v[EH];
    #pragma unroll
    for (int j = 0; j < EH; j++) { u[j] = 0.0f; v[j] = 0.0f; }
    #pragma unroll
    for (int k = 0; k < IND; k++) {
        float a = xv[k];
        #pragma unroll
        for (int j = 0; j < EH; j++) {
            u[j] = fmaf(a, w1s[k][j], u[j]);
            v[j] = fmaf(a, w1s[IND + k][j], v[j]);
        }
    }
    size_t base = (size_t)node * (EH / 2) * BB + b;
    #pragma unroll
    for (int p = 0; p < EH / 2; p++) {
        g_u[base + (size_t)p * BB] = make_float2(u[2*p] * NLOG2E, u[2*p+1] * NLOG2E);
        g_v[base + (size_t)p * BB] = make_float2(v[2*p] * NLOG2E, v[2*p+1] * NLOG2E);
    }
    float wmn0 = wmin[0], wmn1 = wmin[1], wmx0 = wmax[0], wmx1 = wmax[1];
    float speed = fmaf(xv[IND-2], wmx0 - wmn0, wmn0);
    float direc = fmaf(xv[IND-1], wmx1 - wmn1, wmn1);
    float sd, cd;
    sincosf(direc, &sd, &cd);
    g_sw[node * BB + b] = make_float2(speed * cd, speed * sd);
}

// 4 lanes per edge; each thread handles batches b0 and b0+4 of one edge.
// 256 threads / 64 edges per block; weights in smem, broadcast LDS.128.
__global__ void __launch_bounds__(256)
k_edge(const float* __restrict__ W1, const float* __restrict__ b1,
       const float* __restrict__ W2, const float* __restrict__ b2,
       const float* __restrict__ Wn) {
    __shared__ ulonglong2 w2s[EH][6];      // [k][j]: pairs 2j,2j+1 (pair 11 pad 0)
    __shared__ ulonglong2 wn2[EO][4];
    __shared__ ulonglong2 r32s[8], r33s[8], r34s[8], b1s[8];
    __shared__ u64 b2s[11];
    int tid = threadIdx.x;

    for (int i = tid; i < EH * 6; i += 256) {
        int k = i / 6, j = i % 6;
        float a0 = W2[k*EO + 4*j    ] * NLOG2E;
        float a1 = W2[k*EO + 4*j + 1] * NLOG2E;
        float a2 = (4*j + 2 < EO) ? W2[k*EO + 4*j + 2] * NLOG2E : 0.f;
        float a3 = (4*j + 3 < EO) ? W2[k*EO + 4*j + 3] * NLOG2E : 0.f;
        w2s[k][j] = make_ulonglong2(pack2(a0, a1), pack2(a2, a3));
    }
    for (int i = tid; i < EO * 4; i += 256) {
        int r = i / 4, j = i % 4;
        wn2[r][j] = make_ulonglong2(
            pack2(Wn[r*NOUT + 4*j] * NLOG2E,     Wn[r*NOUT + 4*j + 1] * NLOG2E),
            pack2(Wn[r*NOUT + 4*j + 2] * NLOG2E, Wn[r*NOUT + 4*j + 3] * NLOG2E));
    }
    if (tid < 8) {
        int j = tid;
        const float* r32 = W1 + 32 * EH;
        const float* r33 = W1 + 33 * EH;
        const float* r34 = W1 + 34 * EH;
        r32s[j] = make_ulonglong2(pack2(r32[4*j]*NLOG2E, r32[4*j+1]*NLOG2E),
                                  pack2(r32[4*j+2]*NLOG2E, r32[4*j+3]*NLOG2E));
        r33s[j] = make_ulonglong2(pack2(r33[4*j]*NLOG2E, r33[4*j+1]*NLOG2E),
                                  pack2(r33[4*j+2]*NLOG2E, r33[4*j+3]*NLOG2E));
        r34s[j] = make_ulonglong2(pack2(r34[4*j]*NLOG2E, r34[4*j+1]*NLOG2E),
                                  pack2(r34[4*j+2]*NLOG2E, r34[4*j+3]*NLOG2E));
        b1s[j]  = make_ulonglong2(pack2(b1[4*j]*NLOG2E, b1[4*j+1]*NLOG2E),
                                  pack2(b1[4*j+2]*NLOG2E, b1[4*j+3]*NLOG2E));
    }
    if (tid < 11) {
        float c0 = b2[2*tid] * NLOG2E;
        float c1 = (2*tid + 1 < EO) ? b2[2*tid + 1] * NLOG2E : 0.f;
        b2s[tid] = pack2(c0, c1);
    }
    __syncthreads();

    int slot = blockIdx.x * 64 + (tid >> 2);   // 64 edges per 256-thread block
    int b0 = tid & 3;                          // this thread: batches b0, b0+4
    int lane = tid & 31;
    if (slot >= EE) return;

    int2   st  = g_seidx[slot];
    float4 rec = g_serec[slot];
    u64 n0b = bcast2(rec.z), n1b = bcast2(rec.w);

    float2 swA = g_sw[st.x * BB + b0];
    float2 swB = g_sw[st.x * BB + b0 + 4];
    u64 wbA = bcast2(fmaxf(fmaf(rec.x, swA.x, rec.y * swA.y), 0.0f));
    u64 wbB = bcast2(fmaxf(fmaf(rec.x, swB.x, rec.y * swB.y), 0.0f));

    const float2* up = g_u + (size_t)st.x * (EH / 2) * BB + b0;
    const float2* vp = g_v + (size_t)st.y * (EH / 2) * BB + b0;

    u64 eaccA[11], eaccB[11];
    #pragma unroll
    for (int j = 0; j < 11; j++) { eaccA[j] = b2s[j]; eaccB[j] = b2s[j]; }

    for (int pp = 0; pp < 8; pp++) {           // p = 2pp, 2pp+1
        ulonglong2 R32 = r32s[pp], R33 = r33s[pp], R34 = r34s[pp], B1 = b1s[pp];
        #pragma unroll
        for (int h = 0; h < 2; h++) {
            int p = 2 * pp + h;
            u64 rw32 = h ? R32.y : R32.x;
            u64 rw33 = h ? R33.y : R33.x;
            u64 rw34 = h ? R34.y : R34.x;
            u64 bb1  = h ? B1.y  : B1.x;
            u64 tsh = fma2(n1b, rw33, fma2(n0b, rw32, bb1));
            u64 accA = add2(add2(ld2(up + p * BB),     ld2(vp + p * BB)),
                            fma2(wbA, rw34, tsh));
            u64 accB = add2(add2(ld2(up + p * BB + 4), ld2(vp + p * BB + 4)),
                            fma2(wbB, rw34, tsh));
            float aL, aH, bL, bH;
            unpack2(accA, aL, aH); unpack2(accB, bL, bH);
            u64 hA0 = bcast2(sigp(aL)), hA1 = bcast2(sigp(aH));
            u64 hB0 = bcast2(sigp(bL)), hB1 = bcast2(sigp(bH));
            #pragma unroll
            for (int j = 0; j < 5; j++) {       // pairs 2j, 2j+1 (0..9)
                ulonglong2 W0 = w2s[2 * p][j];
                ulonglong2 W1r = w2s[2 * p + 1][j];
                eaccA[2*j]   = fma2(hA0, W0.x,  eaccA[2*j]);
                eaccA[2*j+1] = fma2(hA0, W0.y,  eaccA[2*j+1]);
                eaccA[2*j]   = fma2(hA1, W1r.x, eaccA[2*j]);
                eaccA[2*j+1] = fma2(hA1, W1r.y, eaccA[2*j+1]);
                eaccB[2*j]   = fma2(hB0, W0.x,  eaccB[2*j]);
                eaccB[2*j+1] = fma2(hB0, W0.y,  eaccB[2*j+1]);
                eaccB[2*j]   = fma2(hB1, W1r.x, eaccB[2*j]);
                eaccB[2*j+1] = fma2(hB1, W1r.y, eaccB[2*j+1]);
            }
            {                                   // pair 10 (outputs 20,21)
                ulonglong2 W0 = w2s[2 * p][5];
                ulonglong2 W1r = w2s[2 * p + 1][5];
                eaccA[10] = fma2(hA0, W0.x,  eaccA[10]);
                eaccA[10] = fma2(hA1, W1r.x, eaccA[10]);
                eaccB[10] = fma2(hB0, W0.x,  eaccB[10]);
                eaccB[10] = fma2(hB1, W1r.x, eaccB[10]);
            }
        }
    }

    u64 paccA[8], paccB[8];
    #pragma unroll
    for (int j = 0; j < 8; j++) { paccA[j] = 0ull; paccB[j] = 0ull; }
    #pragma unroll
    for (int q = 0; q < 11; q++) {
        float aL, aH, bL, bH;
        unpack2(eaccA[q], aL, aH); unpack2(eaccB[q], bL, bH);
        u64 eA0 = bcast2(sigp(aL)), eA1 = bcast2(sigp(aH));
        u64 eB0 = bcast2(sigp(bL)), eB1 = bcast2(sigp(bH));
        #pragma unroll
        for (int j = 0; j < 4; j++) {
            ulonglong2 Wa = wn2[2 * q][j];
            ulonglong2 Wb = (2 * q + 1 < EO) ? wn2[2 * q + 1][j]
                                             : make_ulonglong2(0ull, 0ull);
            paccA[2*j]   = fma2(eA0, Wa.x, paccA[2*j]);
            paccA[2*j+1] = fma2(eA0, Wa.y, paccA[2*j+1]);
            paccA[2*j]   = fma2(eA1, Wb.x, paccA[2*j]);
            paccA[2*j+1] = fma2(eA1, Wb.y, paccA[2*j+1]);
            paccB[2*j]   = fma2(eB0, Wa.x, paccB[2*j]);
            paccB[2*j+1] = fma2(eB0, Wa.y, paccB[2*j+1]);
            paccB[2*j]   = fma2(eB1, Wb.x, paccB[2*j]);
            paccB[2*j+1] = fma2(eB1, Wb.y, paccB[2*j+1]);
        }
    }
    float pvA[NOUT], pvB[NOUT];
    #pragma unroll
    for (int j = 0; j < 8; j++) {
        unpack2(paccA[j], pvA[2*j], pvA[2*j+1]);
        unpack2(paccB[j], pvB[2*j], pvB[2*j+1]);
    }

    // tgt scatter: rows are 16 floats; batch b0+4 is +4 rows = +64 floats
    float* at = (float*)(g_agg2 + ((size_t)st.y * BB + b0) * (NOUT / 4));
    #pragma unroll
    for (int q = 0; q < NOUT / 4; q++) {
        red4(at + 4 * q,      pvA[4*q], pvA[4*q+1], pvA[4*q+2], pvA[4*q+3]);
        red4(at + 64 + 4 * q, pvB[4*q], pvB[4*q+1], pvB[4*q+2], pvB[4*q+3]);
    }

    // src scatter: segmented reduction over sorted src runs (stride-4 lanes)
    const unsigned m = 0xFFFFFFFFu;
    int src = st.x;
    #pragma unroll
    for (int q = 0; q < NOUT; q++) { pvA[q] = -pvA[q]; pvB[q] = -pvB[q]; }
    int s4 = __shfl_down_sync(m, src, 4);
    bool e4 = (lane < 28) && (s4 == src);
    #pragma unroll
    for (int q = 0; q < NOUT; q++) {
        float tA = __shfl_down_sync(m, pvA[q], 4);
        float tB = __shfl_down_sync(m, pvB[q], 4);
        if (e4) { pvA[q] += tA; pvB[q] += tB; }
    }
    int s8 = __shfl_down_sync(m, src, 8);
    bool e8 = (lane < 24) && (s8 == src);
    #pragma unroll
    for (int q = 0; q < NOUT; q++) {
        float tA = __shfl_down_sync(m, pvA[q], 8);
        float tB = __shfl_down_sync(m, pvB[q], 8);
        if (e8) { pvA[q] += tA; pvB[q] += tB; }
    }
    int s16 = __shfl_down_sync(m, src, 16);
    bool e16 = (lane < 16) && (s16 == src);
    #pragma unroll
    for (int q = 0; q < NOUT; q++) {
        float tA = __shfl_down_sync(m, pvA[q], 16);
        float tB = __shfl_down_sync(m, pvB[q], 16);
        if (e16) { pvA[q] += tA; pvB[q] += tB; }
    }
    int sprev = __shfl_up_sync(m, src, 4);
    bool leader = (lane < 4) || (sprev != src);
    if (leader) {
        float* as = (float*)(g_agg2 + ((size_t)src * BB + b0) * (NOUT / 4));
        #pragma unroll
        for (int q = 0; q < NOUT / 4; q++) {
            red4(as + 4 * q,      pvA[4*q], pvA[4*q+1], pvA[4*q+2], pvA[4*q+3]);
            red4(as + 64 + 4 * q, pvB[4*q], pvB[4*q+1], pvB[4*q+2], pvB[4*q+3]);
        }
    }
}

// transpose [n][b][16] -> out [b][n][16], fused bias+sigmoid (scaled domain)
__global__ void k_out(const float* __restrict__ bn, float* __restrict__ out) {
    int i = blockIdx.x * blockDim.x + threadIdx.x;
    if (i >= NN * BB * (NOUT / 4)) return;
    float4 v = g_agg2[i];
    int q = i & 3;
    int b = (i >> 2) & 7;
    int n = i >> 5;
    int o = q * 4;
    v.x = sigp(v.x + __ldg(bn + o)     * NLOG2E);
    v.y = sigp(v.y + __ldg(bn + o + 1) * NLOG2E);
    v.z = sigp(v.z + __ldg(bn + o + 2) * NLOG2E);
    v.w = sigp(v.w + __ldg(bn + o + 3) * NLOG2E);
    ((float4*)out)[((size_t)b * NN + n) * (NOUT / 4) + q] = v;
}

// ---------------- launch ----------------
extern "C" void kernel_launch(void* const* d_in, const int* in_sizes, int n_in,
                              void* d_out, int out_size) {
    const float* x    = (const float*)d_in[0];
    const int*   ew32 = (const int*)d_in[1];
    const float* ea   = (const float*)d_in[2];
    const float* wmin = (const float*)d_in[3];
    const float* wmax = (const float*)d_in[4];
    const float* W1   = (const float*)d_in[5];
    const float* b1   = (const float*)d_in[6];
    const float* W2   = (const float*)d_in[7];
    const float* b2   = (const float*)d_in[8];
    const float* Wn   = (const float*)d_in[9];
    const float* bn   = (const float*)d_in[10];
    float* out = (float*)d_out;

    k_init<<<40, 256>>>();
    k_minmax<<<256, 256>>>(ew32, ea);
    k_erec<<<(EE + 255) / 256, 256>>>(ew32, ea);
    k_scan<<<1, 1024>>>();
    k_place<<<(EE + 255) / 256, 256>>>();
    k_node<<<(BB * NN + 255) / 256, 256>>>(x, W1, wmin, wmax);
    k_edge<<<(EE + 63) / 64, 256>>>(W1, b1, W2, b2, Wn);
    k_out<<<(NN * BB * (NOUT / 4) + 255) / 256, 256>>>(bn, out);
}

// round 16
// speedup vs baseline: 1.0789x; 1.0789x over previous
#include <cuda_runtime.h>
#include <math.h>

#define BB 8
#define NN 10000
#define EE 320000
#define IND 16
#define EH 32
#define EO 22
#define NOUT 16

typedef unsigned long long u64;

#define NLOG2E (-1.4426950408889634f)

// ---------------- scratch (device globals; no allocations) ----------------
__device__ float2 g_u[NN * (EH / 2) * BB];   // [node][p][b], pre-scaled by -log2e
__device__ float2 g_v[NN * (EH / 2) * BB];
__device__ float2 g_sw[NN * BB];             // (speed*cos, speed*sin)
__device__ float4 g_agg2[NN * BB * (NOUT / 4)];  // accumulator [n][b][16] (scaled)
__device__ float4 g_erec[EE];                // {cosc/dist, sinc/dist, n0, n1}
__device__ int2   g_eidx[EE];
__device__ float4 g_serec[EE];               // sorted-by-src
__device__ int2   g_seidx[EE];
__device__ int    g_minmax[4];
__device__ int    g_is_i32;
__device__ int    g_cnt[NN];
__device__ int    g_off[NN];

// ---------------- f32x2 helpers ----------------
__device__ __forceinline__ u64 pack2(float lo, float hi) {
    u64 r; asm("mov.b64 %0, {%1, %2};" : "=l"(r) : "f"(lo), "f"(hi)); return r;
}
__device__ __forceinline__ u64 bcast2(float v) { return pack2(v, v); }
__device__ __forceinline__ void unpack2(u64 v, float& lo, float& hi) {
    asm("mov.b64 {%0, %1}, %2;" : "=f"(lo), "=f"(hi) : "l"(v));
}
__device__ __forceinline__ u64 fma2(u64 a, u64 b, u64 c) {
    u64 d; asm("fma.rn.f32x2 %0, %1, %2, %3;" : "=l"(d) : "l"(a), "l"(b), "l"(c)); return d;
}
__device__ __forceinline__ u64 add2(u64 a, u64 b) {
    u64 d; asm("add.rn.f32x2 %0, %1, %2;" : "=l"(d) : "l"(a), "l"(b)); return d;
}
__device__ __forceinline__ u64 ld2(const float2* p) {
    float2 t = *p; return pack2(t.x, t.y);
}
__device__ __forceinline__ void red4(float* p, float a, float b, float c, float d) {
    asm volatile("red.global.add.v4.f32 [%0], {%1, %2, %3, %4};"
                 :: "l"(p), "f"(a), "f"(b), "f"(c), "f"(d) : "memory");
}

// sigmoid with -log2e pre-folded into the argument: sig = rcp(1 + 2^x)
__device__ __forceinline__ float sigp(float x) {
    float e, r;
    asm("ex2.approx.f32 %0, %1;" : "=f"(e) : "f"(x));
    asm("rcp.approx.f32 %0, %1;" : "=f"(r) : "f"(1.0f + e));
    return r;
}

// ---------------- kernels ----------------
// coalesced agg zero + cnt zero + scalar init (R13 layout)
__global__ void k_init() {
    int i = blockIdx.x * blockDim.x + threadIdx.x;
    int stride = gridDim.x * blockDim.x;
    float4 z = make_float4(0.f, 0.f, 0.f, 0.f);
    for (int j = i; j < BB * NN * (NOUT / 4); j += stride) g_agg2[j] = z;
    for (int j = i; j < NN; j += stride) g_cnt[j] = 0;
    if (blockIdx.x == 0 && threadIdx.x == 0) {
        g_minmax[0] = 0x7F800000; g_minmax[1] = 0x7F800000;
        g_minmax[2] = 0;          g_minmax[3] = 0;
        g_is_i32 = 0;
    }
}

// fused: int32/int64 sniff + edge_attr min/max in one kernel
__global__ void k_minmax(const int* __restrict__ w32, const float* __restrict__ ea) {
    int i0 = blockIdx.x * blockDim.x + threadIdx.x;
    int stride = gridDim.x * blockDim.x;
    int hit = 0;
    for (int i = i0; i < EE; i += stride) hit |= (w32[2 * i + 1] != 0);
    float mn0 = 1e30f, mn1 = 1e30f, mx0 = -1e30f, mx1 = -1e30f;
    for (int i = i0; i < EE; i += stride) {
        float a = ea[2 * i], b = ea[2 * i + 1];
        mn0 = fminf(mn0, a); mx0 = fmaxf(mx0, a);
        mn1 = fminf(mn1, b); mx1 = fmaxf(mx1, b);
    }
    #pragma unroll
    for (int o = 16; o; o >>= 1) {
        mn0 = fminf(mn0, __shfl_xor_sync(0xFFFFFFFFu, mn0, o));
        mn1 = fminf(mn1, __shfl_xor_sync(0xFFFFFFFFu, mn1, o));
        mx0 = fmaxf(mx0, __shfl_xor_sync(0xFFFFFFFFu, mx0, o));
        mx1 = fmaxf(mx1, __shfl_xor_sync(0xFFFFFFFFu, mx1, o));
    }
    if ((threadIdx.x & 31) == 0) {
        atomicMin(&g_minmax[0], __float_as_int(mn0));
        atomicMin(&g_minmax[1], __float_as_int(mn1));
        atomicMax(&g_minmax[2], __float_as_int(mx0));
        atomicMax(&g_minmax[3], __float_as_int(mx1));
    }
    hit = __syncthreads_or(hit);
    if (threadIdx.x == 0 && hit) g_is_i32 = 1;
}

__global__ void k_erec(const int* __restrict__ ew32, const float* __restrict__ ea) {
    int e = blockIdx.x * blockDim.x + threadIdx.x;
    if (e >= EE) return;
    float d = ea[2 * e], dir = ea[2 * e + 1];
    float mn0 = __int_as_float(g_minmax[0]), mn1 = __int_as_float(g_minmax[1]);
    float mx0 = __int_as_float(g_minmax[2]), mx1 = __int_as_float(g_minmax[3]);
    float n0 = (d - mn0) / (mx0 - mn0);
    float n1 = (dir - mn1) / (mx1 - mn1);
    float sd, cd;
    sincosf(dir, &sd, &cd);
    float inv = 1.0f / d;
    g_erec[e] = make_float4(cd * inv, sd * inv, n0, n1);
    int s, t;
    if (g_is_i32) { s = ew32[e];     t = ew32[EE + e]; }
    else          { s = ew32[2 * e]; t = ew32[2 * (EE + e)]; }
    s = min(max(s, 0), NN - 1);
    t = min(max(t, 0), NN - 1);
    g_eidx[e] = make_int2(s, t);
    atomicAdd(&g_cnt[s], 1);
}

__global__ void k_scan() {
    __shared__ int ps[1024];
    int tid = threadIdx.x;
    int base = tid * 10;
    int loc[10]; int s = 0;
    #pragma unroll
    for (int i = 0; i < 10; i++) {
        int idx = base + i;
        int c = (idx < NN) ? g_cnt[idx] : 0;
        loc[i] = s; s += c;
    }
    ps[tid] = s;
    int total = s;
    __syncthreads();
    for (int off = 1; off < 1024; off <<= 1) {
        int t = (tid >= off) ? ps[tid - off] : 0;
        __syncthreads();
        ps[tid] += t;
        __syncthreads();
    }
    int excl = ps[tid] - total;
    #pragma unroll
    for (int i = 0; i < 10; i++) {
        int idx = base + i;
        if (idx < NN) g_off[idx] = excl + loc[i];
    }
}

__global__ void k_place() {
    int e = blockIdx.x * blockDim.x + threadIdx.x;
    if (e >= EE) return;
    int2 st = g_eidx[e];
    int pos = atomicAdd(&g_off[st.x], 1);
    g_seidx[pos] = st;
    g_serec[pos] = g_erec[e];
}

__global__ void k_node(const float* __restrict__ x, const float* __restrict__ W1,
                       const float* __restrict__ wmin, const float* __restrict__ wmax) {
    __shared__ float w1s[2 * IND][EH];
    for (int i = threadIdx.x; i < 2 * IND * EH; i += blockDim.x)
        w1s[i / EH][i % EH] = W1[i];
    __syncthreads();
    int idx = blockIdx.x * blockDim.x + threadIdx.x;
    if (idx >= BB * NN) return;
    int b = idx / NN, node = idx - b * NN;
    float xv[IND];
    const float4* xp = (const float4*)(x + (size_t)idx * IND);
    #pragma unroll
    for (int q = 0; q < 4; q++) {
        float4 t = xp[q];
        xv[4*q] = t.x; xv[4*q+1] = t.y; xv[4*q+2] = t.z; xv[4*q+3] = t.w;
    }
    float u[EH], v[EH];
    #pragma unroll
    for (int j = 0; j < EH; j++) { u[j] = 0.0f; v[j] = 0.0f; }
    #pragma unroll
    for (int k = 0; k < IND; k++) {
        float a = xv[k];
        #pragma unroll
        for (int j = 0; j < EH; j++) {
            u[j] = fmaf(a, w1s[k][j], u[j]);
            v[j] = fmaf(a, w1s[IND + k][j], v[j]);
        }
    }
    size_t base = (size_t)node * (EH / 2) * BB + b;
    #pragma unroll
    for (int p = 0; p < EH / 2; p++) {
        g_u[base + (size_t)p * BB] = make_float2(u[2*p] * NLOG2E, u[2*p+1] * NLOG2E);
        g_v[base + (size_t)p * BB] = make_float2(v[2*p] * NLOG2E, v[2*p+1] * NLOG2E);
    }
    float wmn0 = wmin[0], wmn1 = wmin[1], wmx0 = wmax[0], wmx1 = wmax[1];
    float speed = fmaf(xv[IND-2], wmx0 - wmn0, wmn0);
    float direc = fmaf(xv[IND-1], wmx1 - wmn1, wmn1);
    float sd, cd;
    sincosf(direc, &sd, &cd);
    g_sw[node * BB + b] = make_float2(speed * cd, speed * sd);
}

// 4 lanes per edge; each thread handles batches b0 and b0+4 of one edge.
// R13-proven config: 128 threads / 32 edges per block.
__global__ void __launch_bounds__(128)
k_edge(const float* __restrict__ W1, const float* __restrict__ b1,
       const float* __restrict__ W2, const float* __restrict__ b2,
       const float* __restrict__ Wn) {
    __shared__ ulonglong2 w2s[EH][6];      // [k][j]: pairs q=2j,2j+1 (q=11 pad 0)
    __shared__ ulonglong2 wn2[EO][4];
    __shared__ ulonglong2 r32s[8], r33s[8], r34s[8], b1s[8];
    __shared__ u64 b2s[12];
    int tid = threadIdx.x;

    for (int i = tid; i < EH * 6; i += 128) {
        int k = i / 6, j = i % 6;
        float a0 = W2[k*EO + 4*j    ] * NLOG2E;
        float a1 = W2[k*EO + 4*j + 1] * NLOG2E;
        float a2 = (4*j + 2 < EO) ? W2[k*EO + 4*j + 2] * NLOG2E : 0.f;
        float a3 = (4*j + 3 < EO) ? W2[k*EO + 4*j + 3] * NLOG2E : 0.f;
        w2s[k][j] = make_ulonglong2(pack2(a0, a1), pack2(a2, a3));
    }
    for (int i = tid; i < EO * 4; i += 128) {
        int r = i / 4, j = i % 4;
        wn2[r][j] = make_ulonglong2(
            pack2(Wn[r*NOUT + 4*j] * NLOG2E,     Wn[r*NOUT + 4*j + 1] * NLOG2E),
            pack2(Wn[r*NOUT + 4*j + 2] * NLOG2E, Wn[r*NOUT + 4*j + 3] * NLOG2E));
    }
    if (tid < 8) {
        int j = tid;
        const float* r32 = W1 + 32 * EH;
        const float* r33 = W1 + 33 * EH;
        const float* r34 = W1 + 34 * EH;
        r32s[j] = make_ulonglong2(pack2(r32[4*j]*NLOG2E, r32[4*j+1]*NLOG2E),
                                  pack2(r32[4*j+2]*NLOG2E, r32[4*j+3]*NLOG2E));
        r33s[j] = make_ulonglong2(pack2(r33[4*j]*NLOG2E, r33[4*j+1]*NLOG2E),
                                  pack2(r33[4*j+2]*NLOG2E, r33[4*j+3]*NLOG2E));
        r34s[j] = make_ulonglong2(pack2(r34[4*j]*NLOG2E, r34[4*j+1]*NLOG2E),
                                  pack2(r34[4*j+2]*NLOG2E, r34[4*j+3]*NLOG2E));
        b1s[j]  = make_ulonglong2(pack2(b1[4*j]*NLOG2E, b1[4*j+1]*NLOG2E),
                                  pack2(b1[4*j+2]*NLOG2E, b1[4*j+3]*NLOG2E));
    }
    if (tid < 12) {
        float c0 = (2*tid     < EO) ? b2[2*tid]     * NLOG2E : 0.f;
        float c1 = (2*tid + 1 < EO) ? b2[2*tid + 1] * NLOG2E : 0.f;
        b2s[tid] = pack2(c0, c1);
    }
    __syncthreads();

    int slot = blockIdx.x * 32 + (tid >> 2);   // 32 edges per 128-thread block
    int b0 = tid & 3;                          // this thread: batches b0, b0+4
    int lane = tid & 31;
    if (slot >= EE) return;

    int2   st  = g_seidx[slot];
    float4 rec = g_serec[slot];
    u64 n0b = bcast2(rec.z), n1b = bcast2(rec.w);

    float2 swA = g_sw[st.x * BB + b0];
    float2 swB = g_sw[st.x * BB + b0 + 4];
    u64 wbA = bcast2(fmaxf(fmaf(rec.x, swA.x, rec.y * swA.y), 0.0f));
    u64 wbB = bcast2(fmaxf(fmaf(rec.x, swB.x, rec.y * swB.y), 0.0f));

    const float2* up = g_u + (size_t)st.x * (EH / 2) * BB + b0;
    const float2* vp = g_v + (size_t)st.y * (EH / 2) * BB + b0;

    u64 eaccA[12], eaccB[12];
    #pragma unroll
    for (int j = 0; j < 12; j++) { eaccA[j] = b2s[j]; eaccB[j] = b2s[j]; }

    for (int pp = 0; pp < 8; pp++) {           // p = 2pp, 2pp+1
        ulonglong2 R32 = r32s[pp], R33 = r33s[pp], R34 = r34s[pp], B1 = b1s[pp];
        #pragma unroll
        for (int h = 0; h < 2; h++) {
            int p = 2 * pp + h;
            u64 rw32 = h ? R32.y : R32.x;
            u64 rw33 = h ? R33.y : R33.x;
            u64 rw34 = h ? R34.y : R34.x;
            u64 bb1  = h ? B1.y  : B1.x;
            u64 tsh = fma2(n1b, rw33, fma2(n0b, rw32, bb1));
            u64 accA = add2(add2(ld2(up + p * BB),     ld2(vp + p * BB)),
                            fma2(wbA, rw34, tsh));
            u64 accB = add2(add2(ld2(up + p * BB + 4), ld2(vp + p * BB + 4)),
                            fma2(wbB, rw34, tsh));
            float aL, aH, bL, bH;
            unpack2(accA, aL, aH); unpack2(accB, bL, bH);
            u64 hA0 = bcast2(sigp(aL)), hA1 = bcast2(sigp(aH));
            u64 hB0 = bcast2(sigp(bL)), hB1 = bcast2(sigp(bH));
            #pragma unroll
            for (int j = 0; j < 6; j++) {
                ulonglong2 W0 = w2s[2 * p][j];
                ulonglong2 W1r = w2s[2 * p + 1][j];
                eaccA[2*j]   = fma2(hA0, W0.x,  eaccA[2*j]);
                eaccA[2*j+1] = fma2(hA0, W0.y,  eaccA[2*j+1]);
                eaccA[2*j]   = fma2(hA1, W1r.x, eaccA[2*j]);
                eaccA[2*j+1] = fma2(hA1, W1r.y, eaccA[2*j+1]);
                eaccB[2*j]   = fma2(hB0, W0.x,  eaccB[2*j]);
                eaccB[2*j+1] = fma2(hB0, W0.y,  eaccB[2*j+1]);
                eaccB[2*j]   = fma2(hB1, W1r.x, eaccB[2*j]);
                eaccB[2*j+1] = fma2(hB1, W1r.y, eaccB[2*j+1]);
            }
        }
    }

    u64 paccA[8], paccB[8];
    #pragma unroll
    for (int j = 0; j < 8; j++) { paccA[j] = 0ull; paccB[j] = 0ull; }
    #pragma unroll
    for (int q = 0; q < 11; q++) {
        float aL, aH, bL, bH;
        unpack2(eaccA[q], aL, aH); unpack2(eaccB[q], bL, bH);
        u64 eA0 = bcast2(sigp(aL)), eA1 = bcast2(sigp(aH));
        u64 eB0 = bcast2(sigp(bL)), eB1 = bcast2(sigp(bH));
        #pragma unroll
        for (int j = 0; j < 4; j++) {
            ulonglong2 Wa = wn2[2 * q][j];
            ulonglong2 Wb = wn2[2 * q + 1][j];
            paccA[2*j]   = fma2(eA0, Wa.x, paccA[2*j]);
            paccA[2*j+1] = fma2(eA0, Wa.y, paccA[2*j+1]);
            paccA[2*j]   = fma2(eA1, Wb.x, paccA[2*j]);
            paccA[2*j+1] = fma2(eA1, Wb.y, paccA[2*j+1]);
            paccB[2*j]   = fma2(eB0, Wa.x, paccB[2*j]);
            paccB[2*j+1] = fma2(eB0, Wa.y, paccB[2*j+1]);
            paccB[2*j]   = fma2(eB1, Wb.x, paccB[2*j]);
            paccB[2*j+1] = fma2(eB1, Wb.y, paccB[2*j+1]);
        }
    }
    float pvA[NOUT], pvB[NOUT];
    #pragma unroll
    for (int j = 0; j < 8; j++) {
        unpack2(paccA[j], pvA[2*j], pvA[2*j+1]);
        unpack2(paccB[j], pvB[2*j], pvB[2*j+1]);
    }

    // tgt scatter: rows are 16 floats; batch b0+4 is +4 rows = +64 floats
    float* at = (float*)(g_agg2 + ((size_t)st.y * BB + b0) * (NOUT / 4));
    #pragma unroll
    for (int q = 0; q < NOUT / 4; q++) {
        red4(at + 4 * q,      pvA[4*q], pvA[4*q+1], pvA[4*q+2], pvA[4*q+3]);
        red4(at + 64 + 4 * q, pvB[4*q], pvB[4*q+1], pvB[4*q+2], pvB[4*q+3]);
    }

    // src scatter: segmented reduction over sorted src runs (stride-4 lanes)
    const unsigned m = 0xFFFFFFFFu;
    int src = st.x;
    #pragma unroll
    for (int q = 0; q < NOUT; q++) { pvA[q] = -pvA[q]; pvB[q] = -pvB[q]; }
    int s4 = __shfl_down_sync(m, src, 4);
    bool e4 = (lane < 28) && (s4 == src);
    #pragma unroll
    for (int q = 0; q < NOUT; q++) {
        float tA = __shfl_down_sync(m, pvA[q], 4);
        float tB = __shfl_down_sync(m, pvB[q], 4);
        if (e4) { pvA[q] += tA; pvB[q] += tB; }
    }
    int s8 = __shfl_down_sync(m, src, 8);
    bool e8 = (lane < 24) && (s8 == src);
    #pragma unroll
    for (int q = 0; q < NOUT; q++) {
        float tA = __shfl_down_sync(m, pvA[q], 8);
        float tB = __shfl_down_sync(m, pvB[q], 8);
        if (e8) { pvA[q] += tA; pvB[q] += tB; }
    }
    int s16 = __shfl_down_sync(m, src, 16);
    bool e16 = (lane < 16) && (s16 == src);
    #pragma unroll
    for (int q = 0; q < NOUT; q++) {
        float tA = __shfl_down_sync(m, pvA[q], 16);
        float tB = __shfl_down_sync(m, pvB[q], 16);
        if (e16) { pvA[q] += tA; pvB[q] += tB; }
    }
    int sprev = __shfl_up_sync(m, src, 4);
    bool leader = (lane < 4) || (sprev != src);
    if (leader) {
        float* as = (float*)(g_agg2 + ((size_t)src * BB + b0) * (NOUT / 4));
        #pragma unroll
        for (int q = 0; q < NOUT / 4; q++) {
            red4(as + 4 * q,      pvA[4*q], pvA[4*q+1], pvA[4*q+2], pvA[4*q+3]);
            red4(as + 64 + 4 * q, pvB[4*q], pvB[4*q+1], pvB[4*q+2], pvB[4*q+3]);
        }
    }
}

// transpose [n][b][16] -> out [b][n][16], fused bias+sigmoid (scaled domain)
__global__ void k_out(const float* __restrict__ bn, float* __restrict__ out) {
    int i = blockIdx.x * blockDim.x + threadIdx.x;
    if (i >= NN * BB * (NOUT / 4)) return;
    float4 v = g_agg2[i];
    int q = i & 3;
    int b = (i >> 2) & 7;
    int n = i >> 5;
    int o = q * 4;
    v.x = sigp(v.x + __ldg(bn + o)     * NLOG2E);
    v.y = sigp(v.y + __ldg(bn + o + 1) * NLOG2E);
    v.z = sigp(v.z + __ldg(bn + o + 2) * NLOG2E);
    v.w = sigp(v.w + __ldg(bn + o + 3) * NLOG2E);
    ((float4*)out)[((size_t)b * NN + n) * (NOUT / 4) + q] = v;
}

// ---------------- launch ----------------
extern "C" void kernel_launch(void* const* d_in, const int* in_sizes, int n_in,
                              void* d_out, int out_size) {
    const float* x    = (const float*)d_in[0];
    const int*   ew32 = (const int*)d_in[1];
    const float* ea   = (const float*)d_in[2];
    const float* wmin = (const float*)d_in[3];
    const float* wmax = (const float*)d_in[4];
    const float* W1   = (const float*)d_in[5];
    const float* b1   = (const float*)d_in[6];
    const float* W2   = (const float*)d_in[7];
    const float* b2   = (const float*)d_in[8];
    const float* Wn   = (const float*)d_in[9];
    const float* bn   = (const float*)d_in[10];
    float* out = (float*)d_out;

    k_init<<<1024, 256>>>();
    k_minmax<<<256, 256>>>(ew32, ea);
    k_erec<<<(EE + 255) / 256, 256>>>(ew32, ea);
    k_scan<<<1, 1024>>>();
    k_place<<<(EE + 255) / 256, 256>>>();
    k_node<<<(BB * NN + 255) / 256, 256>>>(x, W1, wmin, wmax);
    k_edge<<<(EE + 31) / 32, 128>>>(W1, b1, W2, b2, Wn);
    k_out<<<(NN * BB * (NOUT / 4) + 255) / 256, 256>>>(bn, out);
}